// round 1
// baseline (speedup 1.0000x reference)
#include <cuda_runtime.h>
#include <cuda_bf16.h>
#include <math.h>

#define Bv   64
#define Nv   256
#define Din  16
#define Hv   128
#define Lv   6
#define DFFv 2048
#define HEADSv 8
#define DHv  16
#define TOURLEN 16
#define LSCALE 0.08838834764831845f   /* H^-0.5 */

// -------------------- device scratch (no allocations allowed) --------------------
__device__ float g_h[Bv*Nv*Hv];
__device__ float g_qkv[Bv*Nv*3*Hv];
__device__ float g_att[Bv*Nv*Hv];
__device__ float g_tmp[Bv*Nv*Hv];
__device__ float g_ff[Bv*Nv*DFFv];
__device__ float g_k[Bv*Nv*Hv];
__device__ float g_M[Bv*Nv*Hv];
__device__ float g_baseQ[Bv*Nv*Hv];
__device__ float g_graph[Bv*Hv];
__device__ float g_gq[Bv*Hv];
__device__ float g_W1q[Hv*Hv];
__device__ float g_W2q[Hv*Hv];
__device__ float g_W3q[Hv*Hv];
__device__ float g_bq2[Hv];
__device__ float g_baseL[Bv*Nv*Nv];
__device__ float g_cross[Bv*Nv*Nv];

// -------------------- generic tiled SGEMM: C = A(MxK) @ B(KxN) [+bias][epi] ----
// EPI: 0 = (optional bias), 1 = bias+relu, 2 = bias+residual add
template<int EPI>
__global__ __launch_bounds__(256)
void sgemm64(const float* __restrict__ A, const float* __restrict__ B,
             const float* __restrict__ bias, const float* __restrict__ res,
             float* __restrict__ C, int M, int N, int K)
{
    const int BM = 64, BN = 64, BK = 16;
    __shared__ float As[BK][BM];
    __shared__ float Bs[BK][BN];
    int tid = threadIdx.x;
    int bm = blockIdx.y * BM, bn = blockIdx.x * BN;
    int arow = tid >> 2, acol = (tid & 3) << 2;   // A tile 64x16, 4 floats/thread
    int brow = tid >> 4, bcol = (tid & 15) << 2;  // B tile 16x64, 4 floats/thread
    int tm = (tid >> 4) << 2, tn = (tid & 15) << 2;

    float acc[4][4];
    #pragma unroll
    for (int i = 0; i < 4; i++)
        #pragma unroll
        for (int j = 0; j < 4; j++) acc[i][j] = 0.f;

    const float* Ap = A + (size_t)(bm + arow) * K + acol;
    const float* Bp = B + (size_t)brow * N + bn + bcol;

    for (int k0 = 0; k0 < K; k0 += BK) {
        float4 a4 = *(const float4*)(Ap + k0);
        As[acol + 0][arow] = a4.x;
        As[acol + 1][arow] = a4.y;
        As[acol + 2][arow] = a4.z;
        As[acol + 3][arow] = a4.w;
        float4 b4 = *(const float4*)(Bp + (size_t)k0 * N);
        *(float4*)&Bs[brow][bcol] = b4;
        __syncthreads();
        #pragma unroll
        for (int kk = 0; kk < BK; kk++) {
            float ar[4], br[4];
            #pragma unroll
            for (int i = 0; i < 4; i++) ar[i] = As[kk][tm + i];
            #pragma unroll
            for (int j = 0; j < 4; j++) br[j] = Bs[kk][tn + j];
            #pragma unroll
            for (int i = 0; i < 4; i++)
                #pragma unroll
                for (int j = 0; j < 4; j++) acc[i][j] += ar[i] * br[j];
        }
        __syncthreads();
    }

    #pragma unroll
    for (int i = 0; i < 4; i++) {
        int row = bm + tm + i;
        #pragma unroll
        for (int j = 0; j < 4; j++) {
            int col = bn + tn + j;
            float v = acc[i][j];
            if (bias) v += bias[col];
            if (EPI == 1) v = fmaxf(v, 0.f);
            if (EPI == 2) v += res[(size_t)row * N + col];
            C[(size_t)row * N + col] = v;
        }
    }
}

// -------------------- fused MHA (flash-style, dh=16, N=256) --------------------
__global__ __launch_bounds__(256)
void attn_kernel(const float* __restrict__ qkv, float* __restrict__ out)
{
    int b = blockIdx.x / HEADSv, hd = blockIdx.x % HEADSv;
    __shared__ float Ks[Nv][DHv];
    __shared__ float Vs[Nv][DHv];
    int t = threadIdx.x;  // t = query index / kv row to load
    const float* base = qkv + (size_t)b * Nv * (3 * Hv);
    // load K,V rows (each thread loads 16 consecutive floats via float4)
    {
        const float* krow = base + (size_t)t * (3 * Hv) + Hv + hd * DHv;
        const float* vrow = base + (size_t)t * (3 * Hv) + 2 * Hv + hd * DHv;
        #pragma unroll
        for (int c = 0; c < 4; c++) {
            float4 kv4 = *(const float4*)(krow + c * 4);
            Ks[t][c * 4 + 0] = kv4.x; Ks[t][c * 4 + 1] = kv4.y;
            Ks[t][c * 4 + 2] = kv4.z; Ks[t][c * 4 + 3] = kv4.w;
            float4 vv4 = *(const float4*)(vrow + c * 4);
            Vs[t][c * 4 + 0] = vv4.x; Vs[t][c * 4 + 1] = vv4.y;
            Vs[t][c * 4 + 2] = vv4.z; Vs[t][c * 4 + 3] = vv4.w;
        }
    }
    __syncthreads();

    float q[DHv];
    {
        const float* qrow = base + (size_t)t * (3 * Hv) + hd * DHv;
        #pragma unroll
        for (int d = 0; d < DHv; d++) q[d] = qrow[d];
    }
    float m = -INFINITY, sum = 0.f, acc[DHv];
    #pragma unroll
    for (int d = 0; d < DHv; d++) acc[d] = 0.f;

    for (int j = 0; j < Nv; j++) {
        float s = 0.f;
        #pragma unroll
        for (int d = 0; d < DHv; d++) s += q[d] * Ks[j][d];
        s *= 0.25f;  // dh^-0.5
        float mnew = fmaxf(m, s);
        float corr = expf(m - mnew);
        float p = expf(s - mnew);
        sum = sum * corr + p;
        #pragma unroll
        for (int d = 0; d < DHv; d++) acc[d] = acc[d] * corr + p * Vs[j][d];
        m = mnew;
    }
    float inv = 1.f / sum;
    float* orow = out + ((size_t)b * Nv + t) * Hv + hd * DHv;
    #pragma unroll
    for (int d = 0; d < DHv; d++) orow[d] = acc[d] * inv;
}

// -------------------- layernorm over H=128 --------------------
__global__ __launch_bounds__(128)
void ln_kernel(const float* __restrict__ in, const float* __restrict__ g,
               const float* __restrict__ bt, float* __restrict__ out)
{
    int row = blockIdx.x, t = threadIdx.x;
    float v = in[(size_t)row * Hv + t];
    __shared__ float ws[4];
    int lane = t & 31, wid = t >> 5;
    float s = v;
    #pragma unroll
    for (int o = 16; o > 0; o >>= 1) s += __shfl_xor_sync(0xffffffffu, s, o);
    if (lane == 0) ws[wid] = s;
    __syncthreads();
    float mu = (ws[0] + ws[1] + ws[2] + ws[3]) * (1.f / Hv);
    __syncthreads();
    float d = v - mu;
    float s2 = d * d;
    #pragma unroll
    for (int o = 16; o > 0; o >>= 1) s2 += __shfl_xor_sync(0xffffffffu, s2, o);
    if (lane == 0) ws[wid] = s2;
    __syncthreads();
    float var = (ws[0] + ws[1] + ws[2] + ws[3]) * (1.f / Hv);
    out[(size_t)row * Hv + t] = d * rsqrtf(var + 1e-5f) * g[t] + bt[t];
}

// -------------------- graph mean over N --------------------
__global__ __launch_bounds__(128)
void graph_mean(const float* __restrict__ node, float* __restrict__ graph)
{
    int b = blockIdx.x, h = threadIdx.x;
    float s = 0.f;
    for (int n = 0; n < Nv; n++) s += node[((size_t)b * Nv + n) * Hv + h];
    graph[b * Hv + h] = s * (1.f / Nv);
}

// -------------------- bq2 = bquery @ Wq --------------------
__global__ __launch_bounds__(128)
void vecmat(const float* __restrict__ v, const float* __restrict__ W, float* __restrict__ out)
{
    int j = threadIdx.x;
    float s = 0.f;
    for (int i = 0; i < Hv; i++) s += v[i] * W[i * Hv + j];
    out[j] = s;
}

// -------------------- baseQ += gq[b] --------------------
__global__ void add_gq(float* __restrict__ baseQ, const float* __restrict__ gq)
{
    int idx = blockIdx.x * blockDim.x + threadIdx.x;
    if (idx < Bv * Nv * Hv) {
        int b = idx / (Nv * Hv);
        int h = idx & (Hv - 1);
        baseQ[idx] += gq[b * Hv + h];
    }
}

// -------------------- batched NT gemm: C[b,i,j] = scale * A[b,i,:] . K[b,j,:] ---
__global__ __launch_bounds__(256)
void bgemm_nt(const float* __restrict__ A, const float* __restrict__ Bm,
              float* __restrict__ C, float scale)
{
    int b = blockIdx.z;
    int i0 = blockIdx.y * 32, j0 = blockIdx.x * 32;
    __shared__ float As[32][33];
    __shared__ float Bs[32][33];
    int tid = threadIdx.x;
    int lr = tid >> 3, lc = (tid & 7) << 2;
    int tm = (tid >> 4) << 1, tn = (tid & 15) << 1;
    float acc[2][2] = {{0.f, 0.f}, {0.f, 0.f}};
    const float* Ab = A + ((size_t)b * Nv + i0) * Hv;
    const float* Bb = Bm + ((size_t)b * Nv + j0) * Hv;
    for (int h0 = 0; h0 < Hv; h0 += 32) {
        float4 a4 = *(const float4*)(Ab + (size_t)lr * Hv + h0 + lc);
        As[lr][lc + 0] = a4.x; As[lr][lc + 1] = a4.y; As[lr][lc + 2] = a4.z; As[lr][lc + 3] = a4.w;
        float4 b4 = *(const float4*)(Bb + (size_t)lr * Hv + h0 + lc);
        Bs[lr][lc + 0] = b4.x; Bs[lr][lc + 1] = b4.y; Bs[lr][lc + 2] = b4.z; Bs[lr][lc + 3] = b4.w;
        __syncthreads();
        #pragma unroll
        for (int h = 0; h < 32; h++) {
            float a0 = As[tm][h], a1 = As[tm + 1][h];
            float b0 = Bs[tn][h], b1 = Bs[tn + 1][h];
            acc[0][0] += a0 * b0; acc[0][1] += a0 * b1;
            acc[1][0] += a1 * b0; acc[1][1] += a1 * b1;
        }
        __syncthreads();
    }
    #pragma unroll
    for (int ii = 0; ii < 2; ii++)
        #pragma unroll
        for (int jj = 0; jj < 2; jj++)
            C[((size_t)b * Nv + i0 + tm + ii) * Nv + j0 + tn + jj] = scale * acc[ii][jj];
}

// -------------------- greedy decode: one thread per (b,s) tour --------------------
__global__ __launch_bounds__(256)
void decode_kernel(const float* __restrict__ baseL, const float* __restrict__ cross,
                   float* __restrict__ out_tours, float* __restrict__ out_logp)
{
    int idx = blockIdx.x * blockDim.x + threadIdx.x;
    if (idx >= Bv * Nv) return;
    int b = idx >> 8, s = idx & 255;
    unsigned mask[8] = {0, 0, 0, 0, 0, 0, 0, 0};
    mask[s >> 5] |= 1u << (s & 31);
    const float* bl = baseL + ((size_t)b * Nv + s) * Nv;
    int cur = s;
    float logp = 0.f;
    out_tours[(size_t)idx * TOURLEN] = (float)s;
    for (int step = 1; step < TOURLEN; step++) {
        const float* cr = cross + ((size_t)b * Nv + cur) * Nv;
        float mx = -3.4e38f;
        int arg = 0;
        for (int n = 0; n < Nv; n++) {
            bool vis = (mask[n >> 5] >> (n & 31)) & 1u;
            float v = vis ? -1e9f : (__ldg(bl + n) + __ldg(cr + n));
            if (v > mx) { mx = v; arg = n; }
        }
        float sum = 0.f;
        for (int n = 0; n < Nv; n++) {
            bool vis = (mask[n >> 5] >> (n & 31)) & 1u;
            if (!vis) sum += expf(__ldg(bl + n) + __ldg(cr + n) - mx);
        }
        logp -= logf(sum);
        mask[arg >> 5] |= 1u << (arg & 31);
        cur = arg;
        out_tours[(size_t)idx * TOURLEN + step] = (float)arg;
    }
    out_logp[idx] = logp;
}

// -------------------- host orchestration --------------------
extern "C" void kernel_launch(void* const* d_in, const int* in_sizes, int n_in,
                              void* d_out, int out_size)
{
    const float* x      = (const float*)d_in[0];
    const float* init_W = (const float*)d_in[1];
    const float* init_b = (const float*)d_in[2];
    const float* Wqkv   = (const float*)d_in[3];
    const float* bqkv   = (const float*)d_in[4];
    const float* Wo     = (const float*)d_in[5];
    const float* bo     = (const float*)d_in[6];
    const float* W1     = (const float*)d_in[7];
    const float* b1     = (const float*)d_in[8];
    const float* W2     = (const float*)d_in[9];
    const float* b2     = (const float*)d_in[10];
    const float* ln1_g  = (const float*)d_in[11];
    const float* ln1_b  = (const float*)d_in[12];
    const float* ln2_g  = (const float*)d_in[13];
    const float* ln2_b  = (const float*)d_in[14];
    const float* Wquery = (const float*)d_in[15];
    const float* bquery = (const float*)d_in[16];
    const float* Wq     = (const float*)d_in[17];
    const float* Wk     = (const float*)d_in[18];

    float *h, *qkv, *att, *tmp, *ff, *kbuf, *Mbuf, *baseQ, *graph, *gq;
    float *W1q, *W2q, *W3q, *bq2, *baseL, *cross;
    cudaGetSymbolAddress((void**)&h,     g_h);
    cudaGetSymbolAddress((void**)&qkv,   g_qkv);
    cudaGetSymbolAddress((void**)&att,   g_att);
    cudaGetSymbolAddress((void**)&tmp,   g_tmp);
    cudaGetSymbolAddress((void**)&ff,    g_ff);
    cudaGetSymbolAddress((void**)&kbuf,  g_k);
    cudaGetSymbolAddress((void**)&Mbuf,  g_M);
    cudaGetSymbolAddress((void**)&baseQ, g_baseQ);
    cudaGetSymbolAddress((void**)&graph, g_graph);
    cudaGetSymbolAddress((void**)&gq,    g_gq);
    cudaGetSymbolAddress((void**)&W1q,   g_W1q);
    cudaGetSymbolAddress((void**)&W2q,   g_W2q);
    cudaGetSymbolAddress((void**)&W3q,   g_W3q);
    cudaGetSymbolAddress((void**)&bq2,   g_bq2);
    cudaGetSymbolAddress((void**)&baseL, g_baseL);
    cudaGetSymbolAddress((void**)&cross, g_cross);

    const int Mtok = Bv * Nv;  // 16384

    // ---- init embedding: h = x @ init_W + init_b  (16384 x 128, K=16)
    sgemm64<0><<<dim3(Hv / 64, Mtok / 64), 256>>>(x, init_W, init_b, nullptr, h, Mtok, Hv, Din);

    // ---- encoder layers
    for (int l = 0; l < Lv; l++) {
        sgemm64<0><<<dim3(3 * Hv / 64, Mtok / 64), 256>>>(
            h, Wqkv + (size_t)l * Hv * 3 * Hv, bqkv + (size_t)l * 3 * Hv, nullptr,
            qkv, Mtok, 3 * Hv, Hv);
        attn_kernel<<<Bv * HEADSv, 256>>>(qkv, att);
        sgemm64<2><<<dim3(Hv / 64, Mtok / 64), 256>>>(
            att, Wo + (size_t)l * Hv * Hv, bo + (size_t)l * Hv, h, tmp, Mtok, Hv, Hv);
        ln_kernel<<<Mtok, 128>>>(tmp, ln1_g + (size_t)l * Hv, ln1_b + (size_t)l * Hv, h);
        sgemm64<1><<<dim3(DFFv / 64, Mtok / 64), 256>>>(
            h, W1 + (size_t)l * Hv * DFFv, b1 + (size_t)l * DFFv, nullptr, ff, Mtok, DFFv, Hv);
        sgemm64<2><<<dim3(Hv / 64, Mtok / 64), 256>>>(
            ff, W2 + (size_t)l * DFFv * Hv, b2 + (size_t)l * Hv, h, tmp, Mtok, Hv, DFFv);
        ln_kernel<<<Mtok, 128>>>(tmp, ln2_g + (size_t)l * Hv, ln2_b + (size_t)l * Hv, h);
    }

    // ---- decoder precompute
    graph_mean<<<Bv, 128>>>(h, graph);
    sgemm64<0><<<dim3(Hv / 64, Mtok / 64), 256>>>(h, Wk, nullptr, nullptr, kbuf, Mtok, Hv, Hv);

    // fold Wquery blocks through Wq:  Wiq = Wquery[i] @ Wq
    sgemm64<0><<<dim3(Hv / 64, Hv / 64), 256>>>(Wquery,               Wq, nullptr, nullptr, W1q, Hv, Hv, Hv);
    sgemm64<0><<<dim3(Hv / 64, Hv / 64), 256>>>(Wquery + Hv * Hv,     Wq, nullptr, nullptr, W2q, Hv, Hv, Hv);
    sgemm64<0><<<dim3(Hv / 64, Hv / 64), 256>>>(Wquery + 2 * Hv * Hv, Wq, nullptr, nullptr, W3q, Hv, Hv, Hv);
    vecmat<<<1, 128>>>(bquery, Wq, bq2);

    // gq[b] = graph[b] @ W1q + bq2
    sgemm64<0><<<dim3(Hv / 64, Bv / 64), 256>>>(graph, W1q, bq2, nullptr, gq, Bv, Hv, Hv);
    // baseQ = node @ W2q + gq[b]
    sgemm64<0><<<dim3(Hv / 64, Mtok / 64), 256>>>(h, W2q, nullptr, nullptr, baseQ, Mtok, Hv, Hv);
    add_gq<<<(Bv * Nv * Hv + 255) / 256, 256>>>(baseQ, gq);
    // M = node @ W3q
    sgemm64<0><<<dim3(Hv / 64, Mtok / 64), 256>>>(h, W3q, nullptr, nullptr, Mbuf, Mtok, Hv, Hv);

    // baseL[b,s,n] = scale * baseQ[b,s].k[b,n] ; cross[b,c,n] = scale * M[b,c].k[b,n]
    bgemm_nt<<<dim3(Nv / 32, Nv / 32, Bv), 256>>>(baseQ, kbuf, baseL, LSCALE);
    bgemm_nt<<<dim3(Nv / 32, Nv / 32, Bv), 256>>>(Mbuf,  kbuf, cross, LSCALE);

    // ---- greedy decode, outputs: tours (B*N*16 floats) then logp (B*N floats)
    float* out = (float*)d_out;
    decode_kernel<<<(Bv * Nv + 255) / 256, 256>>>(baseL, cross, out, out + (size_t)Bv * Nv * TOURLEN);
}

// round 2
// speedup vs baseline: 1.0743x; 1.0743x over previous
#include <cuda_runtime.h>
#include <cuda_bf16.h>
#include <math.h>

#define Bv   64
#define Nv   256
#define Din  16
#define Hv   128
#define Lv   6
#define DFFv 2048
#define HEADSv 8
#define DHv  16
#define TOURLEN 16
#define LSCALE 0.08838834764831845f   /* H^-0.5 */

// -------------------- device scratch (no allocations allowed) --------------------
__device__ float g_h[Bv*Nv*Hv];
__device__ float g_qkv[Bv*Nv*3*Hv];
__device__ float g_att[Bv*Nv*Hv];
__device__ float g_ff[Bv*Nv*DFFv];
__device__ float g_k[Bv*Nv*Hv];
__device__ float g_M[Bv*Nv*Hv];
__device__ float g_baseQ[Bv*Nv*Hv];
__device__ float g_graph[Bv*Hv];
__device__ float g_gq[Bv*Hv];
__device__ float g_W1q[Hv*Hv];
__device__ float g_W2q[Hv*Hv];
__device__ float g_W3q[Hv*Hv];
__device__ float g_bq2[Hv];
__device__ float g_baseL[Bv*Nv*Nv];
__device__ float g_cross[Bv*Nv*Nv];

// ============================================================================
// SGEMM, BN=128 fixed, BK=16, 256 threads, double-buffered smem.
// BM=128 -> 8x8 per-thread tile;  BM=64 -> 4x8.
// EPI: 0 = optional bias
//      1 = bias + relu
//      2 = bias + residual + LayerNorm over the 128-wide row (requires N==128)
// ============================================================================
template<int BM, int EPI>
__global__ __launch_bounds__(256)
void sgemm_k(const float* __restrict__ A, const float* __restrict__ B,
             const float* __restrict__ bias, const float* __restrict__ res,
             const float* __restrict__ lng, const float* __restrict__ lnb,
             float* __restrict__ C, int M, int N, int K)
{
    constexpr int TM = BM / 16;                 // rows per thread
    constexpr int NA = (BM * 16) / 1024;        // float4 A-loads per thread
    __shared__ __align__(16) float As[2][16][BM];
    __shared__ __align__(16) float Bs[2][16][128];

    const int tid = threadIdx.x;
    const int tx = tid & 15, ty = tid >> 4;
    const int bm = blockIdx.y * BM;
    const int bn = blockIdx.x * 128;

    const float* Ab = A + (size_t)bm * K;
    const float* Bb = B + bn;

    float4 ra[NA], rb[2];

    // ---- prologue: global load of tile 0
    #pragma unroll
    for (int i = 0; i < NA; i++) {
        int lin = tid + i * 256;
        int r = lin >> 2, c4 = (lin & 3) << 2;
        ra[i] = *(const float4*)(Ab + (size_t)r * K + c4);
    }
    #pragma unroll
    for (int i = 0; i < 2; i++) {
        int lin = tid + i * 256;
        int r = lin >> 5, c4 = (lin & 31) << 2;
        rb[i] = *(const float4*)(Bb + (size_t)r * N + c4);
    }
    #pragma unroll
    for (int i = 0; i < NA; i++) {
        int lin = tid + i * 256;
        int r = lin >> 2, c4 = (lin & 3) << 2;
        As[0][c4 + 0][r] = ra[i].x; As[0][c4 + 1][r] = ra[i].y;
        As[0][c4 + 2][r] = ra[i].z; As[0][c4 + 3][r] = ra[i].w;
    }
    #pragma unroll
    for (int i = 0; i < 2; i++) {
        int lin = tid + i * 256;
        int r = lin >> 5, c4 = (lin & 31) << 2;
        *(float4*)&Bs[0][r][c4] = rb[i];
    }
    __syncthreads();

    float acc[TM][8];
    #pragma unroll
    for (int i = 0; i < TM; i++)
        #pragma unroll
        for (int j = 0; j < 8; j++) acc[i][j] = 0.f;

    int buf = 0;
    for (int k0 = 0; k0 < K; k0 += 16) {
        const bool has_next = (k0 + 16) < K;
        if (has_next) {
            #pragma unroll
            for (int i = 0; i < NA; i++) {
                int lin = tid + i * 256;
                int r = lin >> 2, c4 = (lin & 3) << 2;
                ra[i] = *(const float4*)(Ab + (size_t)r * K + k0 + 16 + c4);
            }
            #pragma unroll
            for (int i = 0; i < 2; i++) {
                int lin = tid + i * 256;
                int r = lin >> 5, c4 = (lin & 31) << 2;
                rb[i] = *(const float4*)(Bb + (size_t)(k0 + 16 + r) * N + c4);
            }
        }
        #pragma unroll
        for (int kk = 0; kk < 16; kk++) {
            float a[TM], b[8];
            #pragma unroll
            for (int i = 0; i < TM; i += 4)
                *(float4*)&a[i] = *(const float4*)&As[buf][kk][ty * TM + i];
            *(float4*)&b[0] = *(const float4*)&Bs[buf][kk][tx * 8];
            *(float4*)&b[4] = *(const float4*)&Bs[buf][kk][tx * 8 + 4];
            #pragma unroll
            for (int i = 0; i < TM; i++)
                #pragma unroll
                for (int j = 0; j < 8; j++) acc[i][j] += a[i] * b[j];
        }
        if (has_next) {
            int nb = buf ^ 1;
            #pragma unroll
            for (int i = 0; i < NA; i++) {
                int lin = tid + i * 256;
                int r = lin >> 2, c4 = (lin & 3) << 2;
                As[nb][c4 + 0][r] = ra[i].x; As[nb][c4 + 1][r] = ra[i].y;
                As[nb][c4 + 2][r] = ra[i].z; As[nb][c4 + 3][r] = ra[i].w;
            }
            #pragma unroll
            for (int i = 0; i < 2; i++) {
                int lin = tid + i * 256;
                int r = lin >> 5, c4 = (lin & 31) << 2;
                *(float4*)&Bs[nb][r][c4] = rb[i];
            }
            __syncthreads();
            buf = nb;
        }
    }

    // ---- epilogue
    float bv[8] = {0.f,0.f,0.f,0.f,0.f,0.f,0.f,0.f};
    if (bias) {
        *(float4*)&bv[0] = *(const float4*)(bias + bn + tx * 8);
        *(float4*)&bv[4] = *(const float4*)(bias + bn + tx * 8 + 4);
    }

    if (EPI == 2) {
        // residual + layernorm over full 128-wide row (N == 128, bn == 0)
        float gv[8], be[8];
        *(float4*)&gv[0] = *(const float4*)(lng + tx * 8);
        *(float4*)&gv[4] = *(const float4*)(lng + tx * 8 + 4);
        *(float4*)&be[0] = *(const float4*)(lnb + tx * 8);
        *(float4*)&be[4] = *(const float4*)(lnb + tx * 8 + 4);
        #pragma unroll
        for (int i = 0; i < TM; i++) {
            int row = bm + ty * TM + i;
            const float* rp = res + (size_t)row * 128 + tx * 8;
            float4 r0 = *(const float4*)rp;
            float4 r1 = *(const float4*)(rp + 4);
            float v[8];
            v[0] = acc[i][0] + bv[0] + r0.x; v[1] = acc[i][1] + bv[1] + r0.y;
            v[2] = acc[i][2] + bv[2] + r0.z; v[3] = acc[i][3] + bv[3] + r0.w;
            v[4] = acc[i][4] + bv[4] + r1.x; v[5] = acc[i][5] + bv[5] + r1.y;
            v[6] = acc[i][6] + bv[6] + r1.z; v[7] = acc[i][7] + bv[7] + r1.w;
            float s = 0.f, s2 = 0.f;
            #pragma unroll
            for (int j = 0; j < 8; j++) { s += v[j]; s2 += v[j] * v[j]; }
            #pragma unroll
            for (int m = 8; m >= 1; m >>= 1) {
                s  += __shfl_xor_sync(0xffffffffu, s,  m);
                s2 += __shfl_xor_sync(0xffffffffu, s2, m);
            }
            float mu  = s * (1.f / 128.f);
            float var = s2 * (1.f / 128.f) - mu * mu;
            float rs  = rsqrtf(var + 1e-5f);
            float o[8];
            #pragma unroll
            for (int j = 0; j < 8; j++) o[j] = (v[j] - mu) * rs * gv[j] + be[j];
            float* cp = C + (size_t)row * 128 + tx * 8;
            *(float4*)cp       = *(float4*)&o[0];
            *(float4*)(cp + 4) = *(float4*)&o[4];
        }
    } else {
        #pragma unroll
        for (int i = 0; i < TM; i++) {
            int row = bm + ty * TM + i;
            float o[8];
            #pragma unroll
            for (int j = 0; j < 8; j++) {
                float v = acc[i][j] + bv[j];
                if (EPI == 1) v = fmaxf(v, 0.f);
                o[j] = v;
            }
            float* cp = C + (size_t)row * N + bn + tx * 8;
            *(float4*)cp       = *(float4*)&o[0];
            *(float4*)(cp + 4) = *(float4*)&o[4];
        }
    }
}

// ============================================================================
// Batched NT GEMM: C[b,i,j] = scale * A[b,i,:] . Kb[b,j,:]   (K = H = 128)
// 128x128 tiles, 256 threads, 8x8 per thread, double buffered.
// ============================================================================
__global__ __launch_bounds__(256)
void bgemm_nt128(const float* __restrict__ A, const float* __restrict__ Kb,
                 float* __restrict__ C, float scale)
{
    __shared__ __align__(16) float As[2][16][128];
    __shared__ __align__(16) float Bs[2][16][128];
    const int tid = threadIdx.x;
    const int tx = tid & 15, ty = tid >> 4;
    const int b = blockIdx.z;
    const int i0 = blockIdx.y * 128, j0 = blockIdx.x * 128;

    const float* Ab = A  + ((size_t)b * Nv + i0) * Hv;
    const float* Kp = Kb + ((size_t)b * Nv + j0) * Hv;

    float4 ra[2], rb[2];
    #pragma unroll
    for (int i = 0; i < 2; i++) {
        int lin = tid + i * 256;
        int r = lin >> 2, c4 = (lin & 3) << 2;
        ra[i] = *(const float4*)(Ab + (size_t)r * Hv + c4);
        rb[i] = *(const float4*)(Kp + (size_t)r * Hv + c4);
    }
    #pragma unroll
    for (int i = 0; i < 2; i++) {
        int lin = tid + i * 256;
        int r = lin >> 2, c4 = (lin & 3) << 2;
        As[0][c4+0][r] = ra[i].x; As[0][c4+1][r] = ra[i].y;
        As[0][c4+2][r] = ra[i].z; As[0][c4+3][r] = ra[i].w;
        Bs[0][c4+0][r] = rb[i].x; Bs[0][c4+1][r] = rb[i].y;
        Bs[0][c4+2][r] = rb[i].z; Bs[0][c4+3][r] = rb[i].w;
    }
    __syncthreads();

    float acc[8][8];
    #pragma unroll
    for (int i = 0; i < 8; i++)
        #pragma unroll
        for (int j = 0; j < 8; j++) acc[i][j] = 0.f;

    int buf = 0;
    for (int k0 = 0; k0 < Hv; k0 += 16) {
        const bool has_next = (k0 + 16) < Hv;
        if (has_next) {
            #pragma unroll
            for (int i = 0; i < 2; i++) {
                int lin = tid + i * 256;
                int r = lin >> 2, c4 = (lin & 3) << 2;
                ra[i] = *(const float4*)(Ab + (size_t)r * Hv + k0 + 16 + c4);
                rb[i] = *(const float4*)(Kp + (size_t)r * Hv + k0 + 16 + c4);
            }
        }
        #pragma unroll
        for (int kk = 0; kk < 16; kk++) {
            float a[8], bb[8];
            *(float4*)&a[0]  = *(const float4*)&As[buf][kk][ty * 8];
            *(float4*)&a[4]  = *(const float4*)&As[buf][kk][ty * 8 + 4];
            *(float4*)&bb[0] = *(const float4*)&Bs[buf][kk][tx * 8];
            *(float4*)&bb[4] = *(const float4*)&Bs[buf][kk][tx * 8 + 4];
            #pragma unroll
            for (int i = 0; i < 8; i++)
                #pragma unroll
                for (int j = 0; j < 8; j++) acc[i][j] += a[i] * bb[j];
        }
        if (has_next) {
            int nb = buf ^ 1;
            #pragma unroll
            for (int i = 0; i < 2; i++) {
                int lin = tid + i * 256;
                int r = lin >> 2, c4 = (lin & 3) << 2;
                As[nb][c4+0][r] = ra[i].x; As[nb][c4+1][r] = ra[i].y;
                As[nb][c4+2][r] = ra[i].z; As[nb][c4+3][r] = ra[i].w;
                Bs[nb][c4+0][r] = rb[i].x; Bs[nb][c4+1][r] = rb[i].y;
                Bs[nb][c4+2][r] = rb[i].z; Bs[nb][c4+3][r] = rb[i].w;
            }
            __syncthreads();
            buf = nb;
        }
    }

    #pragma unroll
    for (int i = 0; i < 8; i++) {
        float* cp = C + ((size_t)b * Nv + i0 + ty * 8 + i) * Nv + j0 + tx * 8;
        float o[8];
        #pragma unroll
        for (int j = 0; j < 8; j++) o[j] = scale * acc[i][j];
        *(float4*)cp       = *(float4*)&o[0];
        *(float4*)(cp + 4) = *(float4*)&o[4];
    }
}

// -------------------- fused MHA (flash-style, dh=16, N=256) --------------------
__global__ __launch_bounds__(256)
void attn_kernel(const float* __restrict__ qkv, float* __restrict__ out)
{
    int b = blockIdx.x / HEADSv, hd = blockIdx.x % HEADSv;
    __shared__ float Ks[Nv][DHv];
    __shared__ float Vs[Nv][DHv];
    int t = threadIdx.x;
    const float* base = qkv + (size_t)b * Nv * (3 * Hv);
    {
        const float* krow = base + (size_t)t * (3 * Hv) + Hv + hd * DHv;
        const float* vrow = base + (size_t)t * (3 * Hv) + 2 * Hv + hd * DHv;
        #pragma unroll
        for (int c = 0; c < 4; c++) {
            float4 kv4 = *(const float4*)(krow + c * 4);
            Ks[t][c * 4 + 0] = kv4.x; Ks[t][c * 4 + 1] = kv4.y;
            Ks[t][c * 4 + 2] = kv4.z; Ks[t][c * 4 + 3] = kv4.w;
            float4 vv4 = *(const float4*)(vrow + c * 4);
            Vs[t][c * 4 + 0] = vv4.x; Vs[t][c * 4 + 1] = vv4.y;
            Vs[t][c * 4 + 2] = vv4.z; Vs[t][c * 4 + 3] = vv4.w;
        }
    }
    __syncthreads();

    float q[DHv];
    {
        const float* qrow = base + (size_t)t * (3 * Hv) + hd * DHv;
        #pragma unroll
        for (int d = 0; d < DHv; d++) q[d] = qrow[d];
    }
    float m = -INFINITY, sum = 0.f, acc[DHv];
    #pragma unroll
    for (int d = 0; d < DHv; d++) acc[d] = 0.f;

    for (int j = 0; j < Nv; j++) {
        float s = 0.f;
        #pragma unroll
        for (int d = 0; d < DHv; d++) s += q[d] * Ks[j][d];
        s *= 0.25f;
        float mnew = fmaxf(m, s);
        float corr = expf(m - mnew);
        float p = expf(s - mnew);
        sum = sum * corr + p;
        #pragma unroll
        for (int d = 0; d < DHv; d++) acc[d] = acc[d] * corr + p * Vs[j][d];
        m = mnew;
    }
    float inv = 1.f / sum;
    float* orow = out + ((size_t)b * Nv + t) * Hv + hd * DHv;
    #pragma unroll
    for (int d = 0; d < DHv; d++) orow[d] = acc[d] * inv;
}

// -------------------- graph mean over N --------------------
__global__ __launch_bounds__(128)
void graph_mean(const float* __restrict__ node, float* __restrict__ graph)
{
    int b = blockIdx.x, h = threadIdx.x;
    float s = 0.f;
    for (int n = 0; n < Nv; n++) s += node[((size_t)b * Nv + n) * Hv + h];
    graph[b * Hv + h] = s * (1.f / Nv);
}

// -------------------- bq2 = bquery @ Wq --------------------
__global__ __launch_bounds__(128)
void vecmat(const float* __restrict__ v, const float* __restrict__ W, float* __restrict__ out)
{
    int j = threadIdx.x;
    float s = 0.f;
    for (int i = 0; i < Hv; i++) s += v[i] * W[i * Hv + j];
    out[j] = s;
}

// -------------------- baseQ += gq[b] --------------------
__global__ void add_gq(float* __restrict__ baseQ, const float* __restrict__ gq)
{
    int idx = blockIdx.x * blockDim.x + threadIdx.x;
    if (idx < Bv * Nv * Hv) {
        int b = idx / (Nv * Hv);
        int h = idx & (Hv - 1);
        baseQ[idx] += gq[b * Hv + h];
    }
}

// -------------------- greedy decode: one thread per (b,s) tour --------------------
__global__ __launch_bounds__(256)
void decode_kernel(const float* __restrict__ baseL, const float* __restrict__ cross,
                   float* __restrict__ out_tours, float* __restrict__ out_logp)
{
    int idx = blockIdx.x * blockDim.x + threadIdx.x;
    if (idx >= Bv * Nv) return;
    int b = idx >> 8, s = idx & 255;
    unsigned mask[8] = {0, 0, 0, 0, 0, 0, 0, 0};
    mask[s >> 5] |= 1u << (s & 31);
    const float* bl = baseL + ((size_t)b * Nv + s) * Nv;
    int cur = s;
    float logp = 0.f;
    out_tours[(size_t)idx * TOURLEN] = (float)s;
    for (int step = 1; step < TOURLEN; step++) {
        const float* cr = cross + ((size_t)b * Nv + cur) * Nv;
        float mx = -3.4e38f;
        int arg = 0;
        for (int n = 0; n < Nv; n++) {
            bool vis = (mask[n >> 5] >> (n & 31)) & 1u;
            float v = vis ? -1e9f : (__ldg(bl + n) + __ldg(cr + n));
            if (v > mx) { mx = v; arg = n; }
        }
        float sum = 0.f;
        for (int n = 0; n < Nv; n++) {
            bool vis = (mask[n >> 5] >> (n & 31)) & 1u;
            if (!vis) sum += expf(__ldg(bl + n) + __ldg(cr + n) - mx);
        }
        logp -= logf(sum);
        mask[arg >> 5] |= 1u << (arg & 31);
        cur = arg;
        out_tours[(size_t)idx * TOURLEN + step] = (float)arg;
    }
    out_logp[idx] = logp;
}

// -------------------- host orchestration --------------------
extern "C" void kernel_launch(void* const* d_in, const int* in_sizes, int n_in,
                              void* d_out, int out_size)
{
    const float* x      = (const float*)d_in[0];
    const float* init_W = (const float*)d_in[1];
    const float* init_b = (const float*)d_in[2];
    const float* Wqkv   = (const float*)d_in[3];
    const float* bqkv   = (const float*)d_in[4];
    const float* Wo     = (const float*)d_in[5];
    const float* bo     = (const float*)d_in[6];
    const float* W1     = (const float*)d_in[7];
    const float* b1     = (const float*)d_in[8];
    const float* W2     = (const float*)d_in[9];
    const float* b2     = (const float*)d_in[10];
    const float* ln1_g  = (const float*)d_in[11];
    const float* ln1_b  = (const float*)d_in[12];
    const float* ln2_g  = (const float*)d_in[13];
    const float* ln2_b  = (const float*)d_in[14];
    const float* Wquery = (const float*)d_in[15];
    const float* bquery = (const float*)d_in[16];
    const float* Wq     = (const float*)d_in[17];
    const float* Wk     = (const float*)d_in[18];

    float *h, *qkv, *att, *ff, *kbuf, *Mbuf, *baseQ, *graph, *gq;
    float *W1q, *W2q, *W3q, *bq2, *baseL, *cross;
    cudaGetSymbolAddress((void**)&h,     g_h);
    cudaGetSymbolAddress((void**)&qkv,   g_qkv);
    cudaGetSymbolAddress((void**)&att,   g_att);
    cudaGetSymbolAddress((void**)&ff,    g_ff);
    cudaGetSymbolAddress((void**)&kbuf,  g_k);
    cudaGetSymbolAddress((void**)&Mbuf,  g_M);
    cudaGetSymbolAddress((void**)&baseQ, g_baseQ);
    cudaGetSymbolAddress((void**)&graph, g_graph);
    cudaGetSymbolAddress((void**)&gq,    g_gq);
    cudaGetSymbolAddress((void**)&W1q,   g_W1q);
    cudaGetSymbolAddress((void**)&W2q,   g_W2q);
    cudaGetSymbolAddress((void**)&W3q,   g_W3q);
    cudaGetSymbolAddress((void**)&bq2,   g_bq2);
    cudaGetSymbolAddress((void**)&baseL, g_baseL);
    cudaGetSymbolAddress((void**)&cross, g_cross);

    const int Mtok = Bv * Nv;  // 16384

    // ---- init embedding: h = x @ init_W + init_b  (16384 x 128, K=16)
    sgemm_k<128, 0><<<dim3(1, Mtok / 128), 256>>>(
        x, init_W, init_b, nullptr, nullptr, nullptr, h, Mtok, Hv, Din);

    // ---- encoder layers
    for (int l = 0; l < Lv; l++) {
        sgemm_k<128, 0><<<dim3(3, Mtok / 128), 256>>>(
            h, Wqkv + (size_t)l * Hv * 3 * Hv, bqkv + (size_t)l * 3 * Hv,
            nullptr, nullptr, nullptr, qkv, Mtok, 3 * Hv, Hv);
        attn_kernel<<<Bv * HEADSv, 256>>>(qkv, att);
        // h = LN(h + att @ Wo + bo)   (residual + LN fused)
        sgemm_k<128, 2><<<dim3(1, Mtok / 128), 256>>>(
            att, Wo + (size_t)l * Hv * Hv, bo + (size_t)l * Hv,
            h, ln1_g + (size_t)l * Hv, ln1_b + (size_t)l * Hv, h, Mtok, Hv, Hv);
        sgemm_k<128, 1><<<dim3(DFFv / 128, Mtok / 128), 256>>>(
            h, W1 + (size_t)l * Hv * DFFv, b1 + (size_t)l * DFFv,
            nullptr, nullptr, nullptr, ff, Mtok, DFFv, Hv);
        // h = LN(h + ff @ W2 + b2)
        sgemm_k<128, 2><<<dim3(1, Mtok / 128), 256>>>(
            ff, W2 + (size_t)l * DFFv * Hv, b2 + (size_t)l * Hv,
            h, ln2_g + (size_t)l * Hv, ln2_b + (size_t)l * Hv, h, Mtok, Hv, DFFv);
    }

    // ---- decoder precompute
    graph_mean<<<Bv, 128>>>(h, graph);
    sgemm_k<128, 0><<<dim3(1, Mtok / 128), 256>>>(
        h, Wk, nullptr, nullptr, nullptr, nullptr, kbuf, Mtok, Hv, Hv);

    // fold Wquery blocks through Wq:  Wiq = Wquery[i] @ Wq
    sgemm_k<64, 0><<<dim3(1, 2), 256>>>(Wquery,               Wq, nullptr, nullptr, nullptr, nullptr, W1q, Hv, Hv, Hv);
    sgemm_k<64, 0><<<dim3(1, 2), 256>>>(Wquery + Hv * Hv,     Wq, nullptr, nullptr, nullptr, nullptr, W2q, Hv, Hv, Hv);
    sgemm_k<64, 0><<<dim3(1, 2), 256>>>(Wquery + 2 * Hv * Hv, Wq, nullptr, nullptr, nullptr, nullptr, W3q, Hv, Hv, Hv);
    vecmat<<<1, 128>>>(bquery, Wq, bq2);

    // gq[b] = graph[b] @ W1q + bq2
    sgemm_k<64, 0><<<dim3(1, 1), 256>>>(graph, W1q, bq2, nullptr, nullptr, nullptr, gq, Bv, Hv, Hv);
    // baseQ = node @ W2q + gq[b]
    sgemm_k<128, 0><<<dim3(1, Mtok / 128), 256>>>(
        h, W2q, nullptr, nullptr, nullptr, nullptr, baseQ, Mtok, Hv, Hv);
    add_gq<<<(Bv * Nv * Hv + 255) / 256, 256>>>(baseQ, gq);
    // M = node @ W3q
    sgemm_k<128, 0><<<dim3(1, Mtok / 128), 256>>>(
        h, W3q, nullptr, nullptr, nullptr, nullptr, Mbuf, Mtok, Hv, Hv);

    // baseL[b,s,n] = scale * baseQ[b,s].k[b,n] ; cross[b,c,n] = scale * M[b,c].k[b,n]
    bgemm_nt128<<<dim3(2, 2, Bv), 256>>>(baseQ, kbuf, baseL, LSCALE);
    bgemm_nt128<<<dim3(2, 2, Bv), 256>>>(Mbuf,  kbuf, cross, LSCALE);

    // ---- greedy decode, outputs: tours (B*N*16 floats) then logp (B*N floats)
    float* out = (float*)d_out;
    decode_kernel<<<(Bv * Nv + 255) / 256, 256>>>(baseL, cross, out, out + (size_t)Bv * Nv * TOURLEN);
}

// round 3
// speedup vs baseline: 1.1288x; 1.0507x over previous
#include <cuda_runtime.h>
#include <cuda_bf16.h>
#include <math.h>

#define Bv   64
#define Nv   256
#define Din  16
#define Hv   128
#define Lv   6
#define DFFv 2048
#define HEADSv 8
#define DHv  16
#define TOURLEN 16
#define LSCALE 0.08838834764831845f   /* H^-0.5 */

// -------------------- device scratch (no allocations allowed) --------------------
__device__ float g_h[Bv*Nv*Hv];
__device__ float g_qkv[Bv*Nv*3*Hv];
__device__ float g_att[Bv*Nv*Hv];
__device__ float g_ff[Bv*Nv*DFFv];
__device__ float g_k[Bv*Nv*Hv];
__device__ float g_M[Bv*Nv*Hv];
__device__ float g_baseQ[Bv*Nv*Hv];
__device__ float g_graph[Bv*Hv];
__device__ float g_gq[Bv*Hv];
__device__ float g_W1q[Hv*Hv];
__device__ float g_W2q[Hv*Hv];
__device__ float g_W3q[Hv*Hv];
__device__ float g_bq2[Hv];
__device__ float g_baseL[Bv*Nv*Nv];
__device__ float g_cross[Bv*Nv*Nv];

// -------------------- packed fp32x2 helpers (Blackwell) --------------------
__device__ __forceinline__ unsigned long long bcast2(float x) {
    unsigned long long r;
    asm("mov.b64 %0, {%1, %1};" : "=l"(r) : "f"(x));
    return r;
}
__device__ __forceinline__ void fma2(unsigned long long& d,
                                     unsigned long long a, unsigned long long b) {
    asm("fma.rn.f32x2 %0, %1, %2, %0;" : "+l"(d) : "l"(a), "l"(b));
}
__device__ __forceinline__ float2 unpk2(unsigned long long v) {
    float lo, hi;
    asm("mov.b64 {%0, %1}, %2;" : "=f"(lo), "=f"(hi) : "l"(v));
    return make_float2(lo, hi);
}

// ============================================================================
// SGEMM, BN=128 fixed, BK=16, 256 threads, double-buffered smem, f32x2 core.
// BM=128 -> 8x8 per-thread tile (as 4 row-pairs x 8);  BM=64 -> 4x8.
// EPI: 0 = optional bias
//      1 = bias + relu
//      2 = bias + residual + LayerNorm over the 128-wide row (requires N==128)
// ============================================================================
template<int BM, int EPI>
__global__ __launch_bounds__(256, 2)
void sgemm_k(const float* __restrict__ A, const float* __restrict__ B,
             const float* __restrict__ bias, const float* __restrict__ res,
             const float* __restrict__ lng, const float* __restrict__ lnb,
             float* __restrict__ C, int M, int N, int K)
{
    constexpr int TM = BM / 16;                 // rows per thread
    constexpr int TP = TM / 2;                  // row-pairs per thread
    constexpr int NA = (BM * 16) / 1024;        // float4 A-loads per thread
    __shared__ __align__(16) float As[2][16][BM];
    __shared__ __align__(16) float Bs[2][16][128];

    const int tid = threadIdx.x;
    const int tx = tid & 15, ty = tid >> 4;
    const int bm = blockIdx.y * BM;
    const int bn = blockIdx.x * 128;

    const float* Ab = A + (size_t)bm * K;
    const float* Bb = B + bn;

    float4 ra[NA], rb[2];

    // ---- prologue: global load of tile 0
    #pragma unroll
    for (int i = 0; i < NA; i++) {
        int lin = tid + i * 256;
        int r = lin >> 2, c4 = (lin & 3) << 2;
        ra[i] = *(const float4*)(Ab + (size_t)r * K + c4);
    }
    #pragma unroll
    for (int i = 0; i < 2; i++) {
        int lin = tid + i * 256;
        int r = lin >> 5, c4 = (lin & 31) << 2;
        rb[i] = *(const float4*)(Bb + (size_t)r * N + c4);
    }
    #pragma unroll
    for (int i = 0; i < NA; i++) {
        int lin = tid + i * 256;
        int r = lin >> 2, c4 = (lin & 3) << 2;
        As[0][c4 + 0][r] = ra[i].x; As[0][c4 + 1][r] = ra[i].y;
        As[0][c4 + 2][r] = ra[i].z; As[0][c4 + 3][r] = ra[i].w;
    }
    #pragma unroll
    for (int i = 0; i < 2; i++) {
        int lin = tid + i * 256;
        int r = lin >> 5, c4 = (lin & 31) << 2;
        *(float4*)&Bs[0][r][c4] = rb[i];
    }
    __syncthreads();

    unsigned long long acc[TP][8];
    #pragma unroll
    for (int i = 0; i < TP; i++)
        #pragma unroll
        for (int j = 0; j < 8; j++) acc[i][j] = 0ull;

    int buf = 0;
    for (int k0 = 0; k0 < K; k0 += 16) {
        const bool has_next = (k0 + 16) < K;
        if (has_next) {
            #pragma unroll
            for (int i = 0; i < NA; i++) {
                int lin = tid + i * 256;
                int r = lin >> 2, c4 = (lin & 3) << 2;
                ra[i] = *(const float4*)(Ab + (size_t)r * K + k0 + 16 + c4);
            }
            #pragma unroll
            for (int i = 0; i < 2; i++) {
                int lin = tid + i * 256;
                int r = lin >> 5, c4 = (lin & 31) << 2;
                rb[i] = *(const float4*)(Bb + (size_t)(k0 + 16 + r) * N + c4);
            }
        }
        #pragma unroll
        for (int kk = 0; kk < 16; kk++) {
            // A fragment: TM consecutive floats = TP packed pairs (row pairs)
            unsigned long long a2[TP];
            #pragma unroll
            for (int i = 0; i < TP; i += 2) {
                ulonglong2 t = *(const ulonglong2*)&As[buf][kk][ty * TM + i * 2];
                a2[i] = t.x; a2[i + 1] = t.y;
            }
            // B fragment: 8 floats, broadcast each into both halves
            float4 bf0 = *(const float4*)&Bs[buf][kk][tx * 8];
            float4 bf1 = *(const float4*)&Bs[buf][kk][tx * 8 + 4];
            unsigned long long bb[8];
            bb[0] = bcast2(bf0.x); bb[1] = bcast2(bf0.y);
            bb[2] = bcast2(bf0.z); bb[3] = bcast2(bf0.w);
            bb[4] = bcast2(bf1.x); bb[5] = bcast2(bf1.y);
            bb[6] = bcast2(bf1.z); bb[7] = bcast2(bf1.w);
            #pragma unroll
            for (int i = 0; i < TP; i++)
                #pragma unroll
                for (int j = 0; j < 8; j++) fma2(acc[i][j], a2[i], bb[j]);
        }
        if (has_next) {
            int nb = buf ^ 1;
            #pragma unroll
            for (int i = 0; i < NA; i++) {
                int lin = tid + i * 256;
                int r = lin >> 2, c4 = (lin & 3) << 2;
                As[nb][c4 + 0][r] = ra[i].x; As[nb][c4 + 1][r] = ra[i].y;
                As[nb][c4 + 2][r] = ra[i].z; As[nb][c4 + 3][r] = ra[i].w;
            }
            #pragma unroll
            for (int i = 0; i < 2; i++) {
                int lin = tid + i * 256;
                int r = lin >> 5, c4 = (lin & 31) << 2;
                *(float4*)&Bs[nb][r][c4] = rb[i];
            }
            __syncthreads();
            buf = nb;
        }
    }

    // ---- epilogue
    float bv[8] = {0.f,0.f,0.f,0.f,0.f,0.f,0.f,0.f};
    if (bias) {
        *(float4*)&bv[0] = *(const float4*)(bias + bn + tx * 8);
        *(float4*)&bv[4] = *(const float4*)(bias + bn + tx * 8 + 4);
    }

    if (EPI == 2) {
        // residual + layernorm over full 128-wide row (N == 128, bn == 0)
        float gv[8], be[8];
        *(float4*)&gv[0] = *(const float4*)(lng + tx * 8);
        *(float4*)&gv[4] = *(const float4*)(lng + tx * 8 + 4);
        *(float4*)&be[0] = *(const float4*)(lnb + tx * 8);
        *(float4*)&be[4] = *(const float4*)(lnb + tx * 8 + 4);
        #pragma unroll
        for (int ip = 0; ip < TP; ip++) {
            #pragma unroll
            for (int e = 0; e < 2; e++) {
                int row = bm + ty * TM + ip * 2 + e;
                const float* rp = res + (size_t)row * 128 + tx * 8;
                float4 r0 = *(const float4*)rp;
                float4 r1 = *(const float4*)(rp + 4);
                float v[8];
                #pragma unroll
                for (int j = 0; j < 8; j++) {
                    float2 p = unpk2(acc[ip][j]);
                    v[j] = (e == 0 ? p.x : p.y) + bv[j];
                }
                v[0] += r0.x; v[1] += r0.y; v[2] += r0.z; v[3] += r0.w;
                v[4] += r1.x; v[5] += r1.y; v[6] += r1.z; v[7] += r1.w;
                float s = 0.f, s2 = 0.f;
                #pragma unroll
                for (int j = 0; j < 8; j++) { s += v[j]; s2 += v[j] * v[j]; }
                #pragma unroll
                for (int m = 8; m >= 1; m >>= 1) {
                    s  += __shfl_xor_sync(0xffffffffu, s,  m);
                    s2 += __shfl_xor_sync(0xffffffffu, s2, m);
                }
                float mu  = s * (1.f / 128.f);
                float var = s2 * (1.f / 128.f) - mu * mu;
                float rs  = rsqrtf(var + 1e-5f);
                float o[8];
                #pragma unroll
                for (int j = 0; j < 8; j++) o[j] = (v[j] - mu) * rs * gv[j] + be[j];
                float* cp = C + (size_t)row * 128 + tx * 8;
                *(float4*)cp       = *(float4*)&o[0];
                *(float4*)(cp + 4) = *(float4*)&o[4];
            }
        }
    } else {
        #pragma unroll
        for (int ip = 0; ip < TP; ip++) {
            #pragma unroll
            for (int e = 0; e < 2; e++) {
                int row = bm + ty * TM + ip * 2 + e;
                float o[8];
                #pragma unroll
                for (int j = 0; j < 8; j++) {
                    float2 p = unpk2(acc[ip][j]);
                    float v = (e == 0 ? p.x : p.y) + bv[j];
                    if (EPI == 1) v = fmaxf(v, 0.f);
                    o[j] = v;
                }
                float* cp = C + (size_t)row * N + bn + tx * 8;
                *(float4*)cp       = *(float4*)&o[0];
                *(float4*)(cp + 4) = *(float4*)&o[4];
            }
        }
    }
}

// ============================================================================
// Batched NT GEMM: C[b,i,j] = scale * A[b,i,:] . Kb[b,j,:]   (K = H = 128)
// 128x128 tiles, 256 threads, 8x8 per thread (f32x2 row pairs), double buffered.
// ============================================================================
__global__ __launch_bounds__(256, 2)
void bgemm_nt128(const float* __restrict__ A, const float* __restrict__ Kb,
                 float* __restrict__ C, float scale)
{
    __shared__ __align__(16) float As[2][16][128];
    __shared__ __align__(16) float Bs[2][16][128];
    const int tid = threadIdx.x;
    const int tx = tid & 15, ty = tid >> 4;
    const int b = blockIdx.z;
    const int i0 = blockIdx.y * 128, j0 = blockIdx.x * 128;

    const float* Ab = A  + ((size_t)b * Nv + i0) * Hv;
    const float* Kp = Kb + ((size_t)b * Nv + j0) * Hv;

    float4 ra[2], rb[2];
    #pragma unroll
    for (int i = 0; i < 2; i++) {
        int lin = tid + i * 256;
        int r = lin >> 2, c4 = (lin & 3) << 2;
        ra[i] = *(const float4*)(Ab + (size_t)r * Hv + c4);
        rb[i] = *(const float4*)(Kp + (size_t)r * Hv + c4);
    }
    #pragma unroll
    for (int i = 0; i < 2; i++) {
        int lin = tid + i * 256;
        int r = lin >> 2, c4 = (lin & 3) << 2;
        As[0][c4+0][r] = ra[i].x; As[0][c4+1][r] = ra[i].y;
        As[0][c4+2][r] = ra[i].z; As[0][c4+3][r] = ra[i].w;
        Bs[0][c4+0][r] = rb[i].x; Bs[0][c4+1][r] = rb[i].y;
        Bs[0][c4+2][r] = rb[i].z; Bs[0][c4+3][r] = rb[i].w;
    }
    __syncthreads();

    unsigned long long acc[4][8];
    #pragma unroll
    for (int i = 0; i < 4; i++)
        #pragma unroll
        for (int j = 0; j < 8; j++) acc[i][j] = 0ull;

    int buf = 0;
    for (int k0 = 0; k0 < Hv; k0 += 16) {
        const bool has_next = (k0 + 16) < Hv;
        if (has_next) {
            #pragma unroll
            for (int i = 0; i < 2; i++) {
                int lin = tid + i * 256;
                int r = lin >> 2, c4 = (lin & 3) << 2;
                ra[i] = *(const float4*)(Ab + (size_t)r * Hv + k0 + 16 + c4);
                rb[i] = *(const float4*)(Kp + (size_t)r * Hv + k0 + 16 + c4);
            }
        }
        #pragma unroll
        for (int kk = 0; kk < 16; kk++) {
            unsigned long long a2[4];
            {
                ulonglong2 t0 = *(const ulonglong2*)&As[buf][kk][ty * 8];
                ulonglong2 t1 = *(const ulonglong2*)&As[buf][kk][ty * 8 + 4];
                a2[0] = t0.x; a2[1] = t0.y; a2[2] = t1.x; a2[3] = t1.y;
            }
            float4 bf0 = *(const float4*)&Bs[buf][kk][tx * 8];
            float4 bf1 = *(const float4*)&Bs[buf][kk][tx * 8 + 4];
            unsigned long long bb[8];
            bb[0] = bcast2(bf0.x); bb[1] = bcast2(bf0.y);
            bb[2] = bcast2(bf0.z); bb[3] = bcast2(bf0.w);
            bb[4] = bcast2(bf1.x); bb[5] = bcast2(bf1.y);
            bb[6] = bcast2(bf1.z); bb[7] = bcast2(bf1.w);
            #pragma unroll
            for (int i = 0; i < 4; i++)
                #pragma unroll
                for (int j = 0; j < 8; j++) fma2(acc[i][j], a2[i], bb[j]);
        }
        if (has_next) {
            int nb = buf ^ 1;
            #pragma unroll
            for (int i = 0; i < 2; i++) {
                int lin = tid + i * 256;
                int r = lin >> 2, c4 = (lin & 3) << 2;
                As[nb][c4+0][r] = ra[i].x; As[nb][c4+1][r] = ra[i].y;
                As[nb][c4+2][r] = ra[i].z; As[nb][c4+3][r] = ra[i].w;
                Bs[nb][c4+0][r] = rb[i].x; Bs[nb][c4+1][r] = rb[i].y;
                Bs[nb][c4+2][r] = rb[i].z; Bs[nb][c4+3][r] = rb[i].w;
            }
            __syncthreads();
            buf = nb;
        }
    }

    #pragma unroll
    for (int ip = 0; ip < 4; ip++) {
        #pragma unroll
        for (int e = 0; e < 2; e++) {
            float* cp = C + ((size_t)b * Nv + i0 + ty * 8 + ip * 2 + e) * Nv + j0 + tx * 8;
            float o[8];
            #pragma unroll
            for (int j = 0; j < 8; j++) {
                float2 p = unpk2(acc[ip][j]);
                o[j] = scale * (e == 0 ? p.x : p.y);
            }
            *(float4*)cp       = *(float4*)&o[0];
            *(float4*)(cp + 4) = *(float4*)&o[4];
        }
    }
}

// -------------------- fused MHA (flash-style, dh=16, N=256) --------------------
__global__ __launch_bounds__(256)
void attn_kernel(const float* __restrict__ qkv, float* __restrict__ out)
{
    int b = blockIdx.x / HEADSv, hd = blockIdx.x % HEADSv;
    __shared__ float Ks[Nv][DHv];
    __shared__ float Vs[Nv][DHv];
    int t = threadIdx.x;
    const float* base = qkv + (size_t)b * Nv * (3 * Hv);
    {
        const float* krow = base + (size_t)t * (3 * Hv) + Hv + hd * DHv;
        const float* vrow = base + (size_t)t * (3 * Hv) + 2 * Hv + hd * DHv;
        #pragma unroll
        for (int c = 0; c < 4; c++) {
            float4 kv4 = *(const float4*)(krow + c * 4);
            Ks[t][c * 4 + 0] = kv4.x; Ks[t][c * 4 + 1] = kv4.y;
            Ks[t][c * 4 + 2] = kv4.z; Ks[t][c * 4 + 3] = kv4.w;
            float4 vv4 = *(const float4*)(vrow + c * 4);
            Vs[t][c * 4 + 0] = vv4.x; Vs[t][c * 4 + 1] = vv4.y;
            Vs[t][c * 4 + 2] = vv4.z; Vs[t][c * 4 + 3] = vv4.w;
        }
    }
    __syncthreads();

    float q[DHv];
    {
        const float* qrow = base + (size_t)t * (3 * Hv) + hd * DHv;
        #pragma unroll
        for (int d = 0; d < DHv; d++) q[d] = qrow[d];
    }
    float m = -INFINITY, sum = 0.f, acc[DHv];
    #pragma unroll
    for (int d = 0; d < DHv; d++) acc[d] = 0.f;

    for (int j = 0; j < Nv; j++) {
        float s = 0.f;
        #pragma unroll
        for (int d = 0; d < DHv; d++) s += q[d] * Ks[j][d];
        s *= 0.25f;
        float mnew = fmaxf(m, s);
        float corr = expf(m - mnew);
        float p = expf(s - mnew);
        sum = sum * corr + p;
        #pragma unroll
        for (int d = 0; d < DHv; d++) acc[d] = acc[d] * corr + p * Vs[j][d];
        m = mnew;
    }
    float inv = 1.f / sum;
    float* orow = out + ((size_t)b * Nv + t) * Hv + hd * DHv;
    #pragma unroll
    for (int d = 0; d < DHv; d++) orow[d] = acc[d] * inv;
}

// -------------------- graph mean over N --------------------
__global__ __launch_bounds__(128)
void graph_mean(const float* __restrict__ node, float* __restrict__ graph)
{
    int b = blockIdx.x, h = threadIdx.x;
    float s = 0.f;
    for (int n = 0; n < Nv; n++) s += node[((size_t)b * Nv + n) * Hv + h];
    graph[b * Hv + h] = s * (1.f / Nv);
}

// -------------------- bq2 = bquery @ Wq --------------------
__global__ __launch_bounds__(128)
void vecmat(const float* __restrict__ v, const float* __restrict__ W, float* __restrict__ out)
{
    int j = threadIdx.x;
    float s = 0.f;
    for (int i = 0; i < Hv; i++) s += v[i] * W[i * Hv + j];
    out[j] = s;
}

// -------------------- baseQ += gq[b] --------------------
__global__ void add_gq(float* __restrict__ baseQ, const float* __restrict__ gq)
{
    int idx = blockIdx.x * blockDim.x + threadIdx.x;
    if (idx < Bv * Nv * Hv) {
        int b = idx / (Nv * Hv);
        int h = idx & (Hv - 1);
        baseQ[idx] += gq[b * Hv + h];
    }
}

// -------------------- greedy decode: one thread per (b,s) tour --------------------
__global__ __launch_bounds__(256)
void decode_kernel(const float* __restrict__ baseL, const float* __restrict__ cross,
                   float* __restrict__ out_tours, float* __restrict__ out_logp)
{
    int idx = blockIdx.x * blockDim.x + threadIdx.x;
    if (idx >= Bv * Nv) return;
    int b = idx >> 8, s = idx & 255;
    unsigned mask[8] = {0, 0, 0, 0, 0, 0, 0, 0};
    mask[s >> 5] |= 1u << (s & 31);
    const float* bl = baseL + ((size_t)b * Nv + s) * Nv;
    int cur = s;
    float logp = 0.f;
    out_tours[(size_t)idx * TOURLEN] = (float)s;
    for (int step = 1; step < TOURLEN; step++) {
        const float* cr = cross + ((size_t)b * Nv + cur) * Nv;
        float mx = -3.4e38f;
        int arg = 0;
        for (int n = 0; n < Nv; n++) {
            bool vis = (mask[n >> 5] >> (n & 31)) & 1u;
            float v = vis ? -1e9f : (__ldg(bl + n) + __ldg(cr + n));
            if (v > mx) { mx = v; arg = n; }
        }
        float sum = 0.f;
        for (int n = 0; n < Nv; n++) {
            bool vis = (mask[n >> 5] >> (n & 31)) & 1u;
            if (!vis) sum += expf(__ldg(bl + n) + __ldg(cr + n) - mx);
        }
        logp -= logf(sum);
        mask[arg >> 5] |= 1u << (arg & 31);
        cur = arg;
        out_tours[(size_t)idx * TOURLEN + step] = (float)arg;
    }
    out_logp[idx] = logp;
}

// -------------------- host orchestration --------------------
extern "C" void kernel_launch(void* const* d_in, const int* in_sizes, int n_in,
                              void* d_out, int out_size)
{
    const float* x      = (const float*)d_in[0];
    const float* init_W = (const float*)d_in[1];
    const float* init_b = (const float*)d_in[2];
    const float* Wqkv   = (const float*)d_in[3];
    const float* bqkv   = (const float*)d_in[4];
    const float* Wo     = (const float*)d_in[5];
    const float* bo     = (const float*)d_in[6];
    const float* W1     = (const float*)d_in[7];
    const float* b1     = (const float*)d_in[8];
    const float* W2     = (const float*)d_in[9];
    const float* b2     = (const float*)d_in[10];
    const float* ln1_g  = (const float*)d_in[11];
    const float* ln1_b  = (const float*)d_in[12];
    const float* ln2_g  = (const float*)d_in[13];
    const float* ln2_b  = (const float*)d_in[14];
    const float* Wquery = (const float*)d_in[15];
    const float* bquery = (const float*)d_in[16];
    const float* Wq     = (const float*)d_in[17];
    const float* Wk     = (const float*)d_in[18];

    float *h, *qkv, *att, *ff, *kbuf, *Mbuf, *baseQ, *graph, *gq;
    float *W1q, *W2q, *W3q, *bq2, *baseL, *cross;
    cudaGetSymbolAddress((void**)&h,     g_h);
    cudaGetSymbolAddress((void**)&qkv,   g_qkv);
    cudaGetSymbolAddress((void**)&att,   g_att);
    cudaGetSymbolAddress((void**)&ff,    g_ff);
    cudaGetSymbolAddress((void**)&kbuf,  g_k);
    cudaGetSymbolAddress((void**)&Mbuf,  g_M);
    cudaGetSymbolAddress((void**)&baseQ, g_baseQ);
    cudaGetSymbolAddress((void**)&graph, g_graph);
    cudaGetSymbolAddress((void**)&gq,    g_gq);
    cudaGetSymbolAddress((void**)&W1q,   g_W1q);
    cudaGetSymbolAddress((void**)&W2q,   g_W2q);
    cudaGetSymbolAddress((void**)&W3q,   g_W3q);
    cudaGetSymbolAddress((void**)&bq2,   g_bq2);
    cudaGetSymbolAddress((void**)&baseL, g_baseL);
    cudaGetSymbolAddress((void**)&cross, g_cross);

    const int Mtok = Bv * Nv;  // 16384

    // ---- init embedding: h = x @ init_W + init_b  (16384 x 128, K=16)
    sgemm_k<128, 0><<<dim3(1, Mtok / 128), 256>>>(
        x, init_W, init_b, nullptr, nullptr, nullptr, h, Mtok, Hv, Din);

    // ---- encoder layers
    for (int l = 0; l < Lv; l++) {
        sgemm_k<128, 0><<<dim3(3, Mtok / 128), 256>>>(
            h, Wqkv + (size_t)l * Hv * 3 * Hv, bqkv + (size_t)l * 3 * Hv,
            nullptr, nullptr, nullptr, qkv, Mtok, 3 * Hv, Hv);
        attn_kernel<<<Bv * HEADSv, 256>>>(qkv, att);
        // h = LN(h + att @ Wo + bo)   (residual + LN fused)
        sgemm_k<128, 2><<<dim3(1, Mtok / 128), 256>>>(
            att, Wo + (size_t)l * Hv * Hv, bo + (size_t)l * Hv,
            h, ln1_g + (size_t)l * Hv, ln1_b + (size_t)l * Hv, h, Mtok, Hv, Hv);
        sgemm_k<128, 1><<<dim3(DFFv / 128, Mtok / 128), 256>>>(
            h, W1 + (size_t)l * Hv * DFFv, b1 + (size_t)l * DFFv,
            nullptr, nullptr, nullptr, ff, Mtok, DFFv, Hv);
        // h = LN(h + ff @ W2 + b2)
        sgemm_k<128, 2><<<dim3(1, Mtok / 128), 256>>>(
            ff, W2 + (size_t)l * DFFv * Hv, b2 + (size_t)l * Hv,
            h, ln2_g + (size_t)l * Hv, ln2_b + (size_t)l * Hv, h, Mtok, Hv, DFFv);
    }

    // ---- decoder precompute
    graph_mean<<<Bv, 128>>>(h, graph);
    sgemm_k<128, 0><<<dim3(1, Mtok / 128), 256>>>(
        h, Wk, nullptr, nullptr, nullptr, nullptr, kbuf, Mtok, Hv, Hv);

    // fold Wquery blocks through Wq:  Wiq = Wquery[i] @ Wq
    sgemm_k<64, 0><<<dim3(1, 2), 256>>>(Wquery,               Wq, nullptr, nullptr, nullptr, nullptr, W1q, Hv, Hv, Hv);
    sgemm_k<64, 0><<<dim3(1, 2), 256>>>(Wquery + Hv * Hv,     Wq, nullptr, nullptr, nullptr, nullptr, W2q, Hv, Hv, Hv);
    sgemm_k<64, 0><<<dim3(1, 2), 256>>>(Wquery + 2 * Hv * Hv, Wq, nullptr, nullptr, nullptr, nullptr, W3q, Hv, Hv, Hv);
    vecmat<<<1, 128>>>(bquery, Wq, bq2);

    // gq[b] = graph[b] @ W1q + bq2
    sgemm_k<64, 0><<<dim3(1, 1), 256>>>(graph, W1q, bq2, nullptr, nullptr, nullptr, gq, Bv, Hv, Hv);
    // baseQ = node @ W2q + gq[b]
    sgemm_k<128, 0><<<dim3(1, Mtok / 128), 256>>>(
        h, W2q, nullptr, nullptr, nullptr, nullptr, baseQ, Mtok, Hv, Hv);
    add_gq<<<(Bv * Nv * Hv + 255) / 256, 256>>>(baseQ, gq);
    // M = node @ W3q
    sgemm_k<128, 0><<<dim3(1, Mtok / 128), 256>>>(
        h, W3q, nullptr, nullptr, nullptr, nullptr, Mbuf, Mtok, Hv, Hv);

    // baseL[b,s,n] = scale * baseQ[b,s].k[b,n] ; cross[b,c,n] = scale * M[b,c].k[b,n]
    bgemm_nt128<<<dim3(2, 2, Bv), 256>>>(baseQ, kbuf, baseL, LSCALE);
    bgemm_nt128<<<dim3(2, 2, Bv), 256>>>(Mbuf,  kbuf, cross, LSCALE);

    // ---- greedy decode, outputs: tours (B*N*16 floats) then logp (B*N floats)
    float* out = (float*)d_out;
    decode_kernel<<<(Bv * Nv + 255) / 256, 256>>>(baseL, cross, out, out + (size_t)Bv * Nv * TOURLEN);
}